// round 4
// baseline (speedup 1.0000x reference)
#include <cuda_runtime.h>

#define B_ 4
#define T_ 2048
#define C_ 1024
#define H_ 16
#define D_ 64
#define M_ (B_*T_)

// Scratch (device globals; allocation-free per harness rules)
__device__ float g_q [B_*H_*T_*D_];   // [B,H,T,d]
__device__ float g_k [B_*H_*T_*D_];
__device__ float g_v [B_*H_*T_*D_];
__device__ float g_ao[M_*C_];         // attention output, [B*T, C]

// ---------------------------------------------------------------------------
// helpers
// ---------------------------------------------------------------------------
__device__ __forceinline__ unsigned f2tf(float x) {
    unsigned r;
    asm("cvt.rna.tf32.f32 %0, %1;" : "=r"(r) : "f"(x));
    return r;
}
__device__ __forceinline__ float f2tf_f(float x) {
    return __uint_as_float(f2tf(x));
}
__device__ __forceinline__ void mma_tf32(float* d, const unsigned* a,
                                         const unsigned* b, const float* c) {
    asm volatile(
        "mma.sync.aligned.m16n8k8.row.col.f32.tf32.tf32.f32 "
        "{%0,%1,%2,%3}, {%4,%5,%6,%7}, {%8,%9}, {%10,%11,%12,%13};\n"
        : "=f"(d[0]), "=f"(d[1]), "=f"(d[2]), "=f"(d[3])
        : "r"(a[0]), "r"(a[1]), "r"(a[2]), "r"(a[3]),
          "r"(b[0]), "r"(b[1]),
          "f"(c[0]), "f"(c[1]), "f"(c[2]), "f"(c[3]));
}
__device__ __forceinline__ void cp_async16(float* smem, const float* gmem) {
    unsigned saddr = (unsigned)__cvta_generic_to_shared(smem);
    asm volatile("cp.async.cg.shared.global [%0], [%1], 16;\n"
                 :: "r"(saddr), "l"(gmem) : "memory");
}
#define CP_COMMIT() asm volatile("cp.async.commit_group;\n" ::: "memory")
#define CP_WAIT(n)  asm volatile("cp.async.wait_group %0;\n" :: "n"(n) : "memory")

// ---------------------------------------------------------------------------
// GEMM: 128x128 block, 4 warps (2x2 of 64x64 warp tiles), 128 threads,
// K-step 32, 3-stage cp.async pipeline, consumer-side tf32 cvt.
// ---------------------------------------------------------------------------
#define GA_LD 36
#define GB_LD 132
#define AS_ST (128*GA_LD)
#define BS_ST (32*GB_LD)
#define G_STAGE (AS_ST + BS_ST)

template<int LDN>
__device__ __forceinline__ void gemm_stage(float* smg, const float* A,
    const float* Wm, int m0, int n0, int ks, int tid)
{
    float* As = smg + (ks % 3) * G_STAGE;
    float* Bs = As + AS_ST;
    const int k0 = ks << 5;
#pragma unroll
    for (int i = 0; i < 8; i++) {            // A tile 128x32
        int id = i*128 + tid;
        int r = id >> 3, cc = (id & 7) << 2;
        cp_async16(&As[r*GA_LD + cc], A + (size_t)(m0 + r)*C_ + k0 + cc);
    }
#pragma unroll
    for (int i = 0; i < 8; i++) {            // B tile 32x128
        int id = i*128 + tid;
        int r = id >> 5, cc = (id & 31) << 2;
        cp_async16(&Bs[r*GB_LD + cc], Wm + (size_t)(k0 + r)*LDN + n0 + cc);
    }
    CP_COMMIT();
}

template<int LDN, bool SCATTER>
__global__ __launch_bounds__(128) void mma_gemm(
    const float* __restrict__ A, const float* __restrict__ Wm,
    const float* __restrict__ bias, float* __restrict__ out)
{
    extern __shared__ float smg[];

    const int tid  = threadIdx.x;
    const int lane = tid & 31, w = tid >> 5;
    const int g = lane >> 2, ctg = lane & 3;
    const int wm = (w >> 1) << 6;     // 0,64
    const int wn = (w & 1)  << 6;     // 0,64
    const int m0 = blockIdx.y << 7, n0 = blockIdx.x << 7;

    float acc[4][8][4];
#pragma unroll
    for (int mt = 0; mt < 4; mt++)
#pragma unroll
        for (int nf = 0; nf < 8; nf++)
#pragma unroll
            for (int r = 0; r < 4; r++) acc[mt][nf][r] = 0.f;

    gemm_stage<LDN>(smg, A, Wm, m0, n0, 0, tid);
    gemm_stage<LDN>(smg, A, Wm, m0, n0, 1, tid);

#pragma unroll 1
    for (int ks = 0; ks < 32; ks++) {
        if (ks + 1 < 32) { CP_WAIT(1); } else { CP_WAIT(0); }
        __syncthreads();
        if (ks + 2 < 32) gemm_stage<LDN>(smg, A, Wm, m0, n0, ks + 2, tid);

        const float* As = smg + (ks % 3) * G_STAGE;
        const float* Bs = As + AS_ST;
#pragma unroll
        for (int kk = 0; kk < 4; kk++) {
            unsigned afr[4][4];
#pragma unroll
            for (int mt = 0; mt < 4; mt++) {
                int rb = wm + (mt << 4);
                afr[mt][0] = f2tf(As[(rb+g  )*GA_LD + (kk<<3) + ctg    ]);
                afr[mt][1] = f2tf(As[(rb+g+8)*GA_LD + (kk<<3) + ctg    ]);
                afr[mt][2] = f2tf(As[(rb+g  )*GA_LD + (kk<<3) + ctg + 4]);
                afr[mt][3] = f2tf(As[(rb+g+8)*GA_LD + (kk<<3) + ctg + 4]);
            }
#pragma unroll
            for (int nf = 0; nf < 8; nf++) {
                unsigned bfr[2];
                bfr[0] = f2tf(Bs[((kk<<3)+ctg  )*GB_LD + wn + (nf<<3) + g]);
                bfr[1] = f2tf(Bs[((kk<<3)+ctg+4)*GB_LD + wn + (nf<<3) + g]);
#pragma unroll
                for (int mt = 0; mt < 4; mt++)
                    mma_tf32(acc[mt][nf], afr[mt], bfr, acc[mt][nf]);
            }
        }
    }

    // Epilogue
#pragma unroll
    for (int mt = 0; mt < 4; mt++) {
#pragma unroll
        for (int nf = 0; nf < 8; nf++) {
            int col = n0 + wn + (nf << 3) + (ctg << 1);
            int r0  = m0 + wm + (mt << 4) + g;
            float b0 = bias[col], b1 = bias[col + 1];
            float2 v0 = make_float2(acc[mt][nf][0] + b0, acc[mt][nf][1] + b1);
            float2 v1 = make_float2(acc[mt][nf][2] + b0, acc[mt][nf][3] + b1);
            if (SCATTER) {
                int sect = col >> 10, cc = col & 1023;
                int h = cc >> 6, dd = cc & 63;
                float* dst = (sect == 0) ? g_q : (sect == 1) ? g_k : g_v;
                int bb0 = r0 >> 11, t0 = r0 & (T_-1);
                int r1 = r0 + 8, bb1 = r1 >> 11, t1 = r1 & (T_-1);
                *(float2*)(dst + (((size_t)bb0*H_ + h)*T_ + t0)*D_ + dd) = v0;
                *(float2*)(dst + (((size_t)bb1*H_ + h)*T_ + t1)*D_ + dd) = v1;
            } else {
                *(float2*)(out + (size_t)r0*LDN + col) = v0;
                *(float2*)(out + (size_t)(r0+8)*LDN + col) = v1;
            }
        }
    }
}

// ---------------------------------------------------------------------------
// Causal flash attention: 4 warps x 32 q-rows = 128-row block, 128 threads.
// 3-stage cp.async K/V pipeline; K/V B-fragments shared across the 2 m16
// sub-tiles; per-warp causal tile skip; exp2-domain softmax.
// ---------------------------------------------------------------------------
#define AK_LD 68
#define AV_LD 72
#define KS_SZ (64*AK_LD)
#define VS_SZ (64*AV_LD)
#define A_STAGE (KS_SZ + VS_SZ)
#define P_LD 68

__device__ __forceinline__ void attn_stage(float* sm, const float* Kg,
                                           const float* Vg, int kt, int tid)
{
    float* Ks = sm + (kt % 3) * A_STAGE;
    float* Vs = Ks + KS_SZ;
    const float* Kt = Kg + (size_t)(kt << 6) * D_;
    const float* Vt = Vg + (size_t)(kt << 6) * D_;
#pragma unroll
    for (int i = 0; i < 8; i++) {
        int id = i*128 + tid;
        int r = id >> 4, cc = (id & 15) << 2;
        cp_async16(&Ks[r*AK_LD + cc], Kt + r*D_ + cc);
        cp_async16(&Vs[r*AV_LD + cc], Vt + r*D_ + cc);
    }
    CP_COMMIT();
}

__global__ __launch_bounds__(128) void attn_mma()
{
    extern __shared__ float sm[];
    float* Ps = sm + 3*A_STAGE;          // per warp [32][P_LD]

    const int tid  = threadIdx.x;
    const int lane = tid & 31, w = tid >> 5;
    const int g = lane >> 2, ctg = lane & 3;
    const int qb = (gridDim.x - 1) - blockIdx.x;   // heavy blocks first
    const int bh = blockIdx.y;
    const int q0 = qb << 7;
    const int wq = q0 + (w << 5);                  // warp's 32 rows
    float* Pw = Ps + w * 32 * P_LD;

    const float* Qg = g_q + (size_t)bh * T_ * D_;
    const float* Kg = g_k + (size_t)bh * T_ * D_;
    const float* Vg = g_v + (size_t)bh * T_ * D_;

    // Q A-fragments; scale = 1/sqrt(64) * log2(e)
    const float qsc = 0.125f * 1.4426950408889634f;
    unsigned aq[8][2][4];
#pragma unroll
    for (int j = 0; j < 8; j++)
#pragma unroll
        for (int mt = 0; mt < 2; mt++) {
            int r0 = wq + (mt << 4) + g;
            aq[j][mt][0] = f2tf(Qg[(r0  )*D_ + (j<<3) + ctg    ] * qsc);
            aq[j][mt][1] = f2tf(Qg[(r0+8)*D_ + (j<<3) + ctg    ] * qsc);
            aq[j][mt][2] = f2tf(Qg[(r0  )*D_ + (j<<3) + ctg + 4] * qsc);
            aq[j][mt][3] = f2tf(Qg[(r0+8)*D_ + (j<<3) + ctg + 4] * qsc);
        }

    float m_i[2][2] = {{-1e30f,-1e30f},{-1e30f,-1e30f}};
    float l_i[2][2] = {{0.f,0.f},{0.f,0.f}};
    float o[2][8][4];
#pragma unroll
    for (int mt = 0; mt < 2; mt++)
#pragma unroll
        for (int nf = 0; nf < 8; nf++)
#pragma unroll
            for (int r = 0; r < 4; r++) o[mt][nf][r] = 0.f;

    const int nkt = (q0 >> 6) + 2;
    attn_stage(sm, Kg, Vg, 0, tid);
    attn_stage(sm, Kg, Vg, 1, tid);

#pragma unroll 1
    for (int kt = 0; kt < nkt; kt++) {
        if (kt + 1 < nkt) { CP_WAIT(1); } else { CP_WAIT(0); }
        __syncthreads();
        if (kt + 2 < nkt) attn_stage(sm, Kg, Vg, kt + 2, tid);

        if ((kt << 6) <= wq + 31) {        // per-warp causal tile skip
            const float* Ksb = sm + (kt % 3) * A_STAGE;
            const float* Vsb = Ksb + KS_SZ;

            // S = Q K^T
            float s[2][8][4];
#pragma unroll
            for (int mt = 0; mt < 2; mt++)
#pragma unroll
                for (int nf = 0; nf < 8; nf++)
#pragma unroll
                    for (int r = 0; r < 4; r++) s[mt][nf][r] = 0.f;
#pragma unroll
            for (int kk = 0; kk < 8; kk++) {
#pragma unroll
                for (int nf = 0; nf < 8; nf++) {
                    unsigned bk[2];
                    bk[0] = f2tf(Ksb[((nf<<3)+g)*AK_LD + (kk<<3) + ctg    ]);
                    bk[1] = f2tf(Ksb[((nf<<3)+g)*AK_LD + (kk<<3) + ctg + 4]);
                    mma_tf32(s[0][nf], aq[kk][0], bk, s[0][nf]);
                    mma_tf32(s[1][nf], aq[kk][1], bk, s[1][nf]);
                }
            }

            // causal mask on diagonal-overlapping tiles
            if ((kt << 6) + 63 > wq) {
#pragma unroll
                for (int mt = 0; mt < 2; mt++)
#pragma unroll
                    for (int nf = 0; nf < 8; nf++) {
                        int col = (kt << 6) + (nf << 3) + (ctg << 1);
                        int r0 = wq + (mt << 4) + g, r1 = r0 + 8;
                        if (col     > r0) s[mt][nf][0] = -1e30f;
                        if (col + 1 > r0) s[mt][nf][1] = -1e30f;
                        if (col     > r1) s[mt][nf][2] = -1e30f;
                        if (col + 1 > r1) s[mt][nf][3] = -1e30f;
                    }
            }

            // online softmax (exp2 domain)
#pragma unroll
            for (int mt = 0; mt < 2; mt++)
#pragma unroll
                for (int rr = 0; rr < 2; rr++) {
                    float mx = -1e30f;
#pragma unroll
                    for (int nf = 0; nf < 8; nf++)
                        mx = fmaxf(mx, fmaxf(s[mt][nf][rr*2], s[mt][nf][rr*2+1]));
                    mx = fmaxf(mx, __shfl_xor_sync(0xffffffffu, mx, 1));
                    mx = fmaxf(mx, __shfl_xor_sync(0xffffffffu, mx, 2));
                    float mn = fmaxf(m_i[mt][rr], mx);
                    float alpha = exp2f(m_i[mt][rr] - mn);
                    m_i[mt][rr] = mn;
                    float rs = 0.f;
#pragma unroll
                    for (int nf = 0; nf < 8; nf++) {
                        float p0 = exp2f(s[mt][nf][rr*2]   - mn);
                        float p1 = exp2f(s[mt][nf][rr*2+1] - mn);
                        s[mt][nf][rr*2] = p0; s[mt][nf][rr*2+1] = p1;
                        rs += p0 + p1;
                    }
                    rs += __shfl_xor_sync(0xffffffffu, rs, 1);
                    rs += __shfl_xor_sync(0xffffffffu, rs, 2);
                    l_i[mt][rr] = l_i[mt][rr]*alpha + rs;
#pragma unroll
                    for (int nf = 0; nf < 8; nf++) {
                        o[mt][nf][rr*2]   *= alpha;
                        o[mt][nf][rr*2+1] *= alpha;
                    }
                }

            // P -> per-warp smem (tf32-rounded)
#pragma unroll
            for (int mt = 0; mt < 2; mt++)
#pragma unroll
                for (int nf = 0; nf < 8; nf++) {
                    int rb = (mt << 4) + g;
                    *(float2*)&Pw[ rb    *P_LD + (nf<<3) + (ctg<<1)] =
                        make_float2(f2tf_f(s[mt][nf][0]), f2tf_f(s[mt][nf][1]));
                    *(float2*)&Pw[(rb+8) *P_LD + (nf<<3) + (ctg<<1)] =
                        make_float2(f2tf_f(s[mt][nf][2]), f2tf_f(s[mt][nf][3]));
                }
            __syncwarp();

            // O += P @ V
#pragma unroll
            for (int kk = 0; kk < 8; kk++) {
                unsigned ap[2][4];
#pragma unroll
                for (int mt = 0; mt < 2; mt++) {
                    int rb = (mt << 4) + g;
                    ap[mt][0] = __float_as_uint(Pw[ rb    *P_LD + (kk<<3) + ctg    ]);
                    ap[mt][1] = __float_as_uint(Pw[(rb+8) *P_LD + (kk<<3) + ctg    ]);
                    ap[mt][2] = __float_as_uint(Pw[ rb    *P_LD + (kk<<3) + ctg + 4]);
                    ap[mt][3] = __float_as_uint(Pw[(rb+8) *P_LD + (kk<<3) + ctg + 4]);
                }
#pragma unroll
                for (int nf = 0; nf < 8; nf++) {
                    unsigned bv[2];
                    bv[0] = f2tf(Vsb[((kk<<3)+ctg  )*AV_LD + (nf<<3) + g]);
                    bv[1] = f2tf(Vsb[((kk<<3)+ctg+4)*AV_LD + (nf<<3) + g]);
                    mma_tf32(o[0][nf], ap[0], bv, o[0][nf]);
                    mma_tf32(o[1][nf], ap[1], bv, o[1][nf]);
                }
            }
        }
    }

    // epilogue: write [B*T, C]
    const int b = bh >> 4, h = bh & 15;
#pragma unroll
    for (int mt = 0; mt < 2; mt++) {
        float inv0 = 1.0f / l_i[mt][0], inv1 = 1.0f / l_i[mt][1];
        int r0 = wq + (mt << 4) + g;
#pragma unroll
        for (int nf = 0; nf < 8; nf++) {
            int dd = (nf << 3) + (ctg << 1);
            size_t base0 = (size_t)(b*T_ + r0    )*C_ + (h << 6) + dd;
            size_t base1 = (size_t)(b*T_ + r0 + 8)*C_ + (h << 6) + dd;
            *(float2*)(g_ao + base0) = make_float2(o[mt][nf][0]*inv0, o[mt][nf][1]*inv0);
            *(float2*)(g_ao + base1) = make_float2(o[mt][nf][2]*inv1, o[mt][nf][3]*inv1);
        }
    }
}

// ---------------------------------------------------------------------------
extern "C" void kernel_launch(void* const* d_in, const int* in_sizes, int n_in,
                              void* d_out, int out_size)
{
    const float* x      = (const float*)d_in[0];
    const float* w_qkv  = (const float*)d_in[1];
    const float* b_qkv  = (const float*)d_in[2];
    const float* w_proj = (const float*)d_in[3];
    const float* b_proj = (const float*)d_in[4];
    float* out = (float*)d_out;

    float* ao_ptr = nullptr;
    cudaGetSymbolAddress((void**)&ao_ptr, g_ao);

    const int gemm_smem = 3 * G_STAGE * (int)sizeof(float);                 // 105984
    const int attn_smem = (3*A_STAGE + 4*32*P_LD) * (int)sizeof(float);     // 142336

    cudaFuncSetAttribute(mma_gemm<3*C_, true>,
                         cudaFuncAttributeMaxDynamicSharedMemorySize, gemm_smem);
    cudaFuncSetAttribute(mma_gemm<C_, false>,
                         cudaFuncAttributeMaxDynamicSharedMemorySize, gemm_smem);
    cudaFuncSetAttribute(attn_mma,
                         cudaFuncAttributeMaxDynamicSharedMemorySize, attn_smem);

    dim3 gq(24, 64);   // N=3072/128, M=8192/128
    mma_gemm<3*C_, true><<<gq, 128, gemm_smem>>>(x, w_qkv, b_qkv, nullptr);

    dim3 ga(16, 64);   // q-blocks (128 rows), B*H
    attn_mma<<<ga, 128, attn_smem>>>();

    dim3 gp(8, 64);    // N=1024/128, M=8192/128
    mma_gemm<C_, false><<<gp, 128, gemm_smem>>>(ao_ptr, w_proj, b_proj, out);
}

// round 5
// speedup vs baseline: 1.0486x; 1.0486x over previous
#include <cuda_runtime.h>

#define B_ 4
#define T_ 2048
#define C_ 1024
#define H_ 16
#define D_ 64
#define M_ (B_*T_)

// Scratch (device globals; allocation-free per harness rules)
__device__ float g_q [B_*H_*T_*D_];   // [B,H,T,d]
__device__ float g_k [B_*H_*T_*D_];
__device__ float g_v [B_*H_*T_*D_];
__device__ float g_ao[M_*C_];         // attention output, [B*T, C]

// ---------------------------------------------------------------------------
// helpers
// ---------------------------------------------------------------------------
__device__ __forceinline__ unsigned f2tf(float x) {
    unsigned r;
    asm("cvt.rna.tf32.f32 %0, %1;" : "=r"(r) : "f"(x));
    return r;
}
__device__ __forceinline__ float f2tf_f(float x) {
    return __uint_as_float(f2tf(x));
}
__device__ __forceinline__ void mma_tf32(float* d, const unsigned* a,
                                         const unsigned* b, const float* c) {
    asm volatile(
        "mma.sync.aligned.m16n8k8.row.col.f32.tf32.tf32.f32 "
        "{%0,%1,%2,%3}, {%4,%5,%6,%7}, {%8,%9}, {%10,%11,%12,%13};\n"
        : "=f"(d[0]), "=f"(d[1]), "=f"(d[2]), "=f"(d[3])
        : "r"(a[0]), "r"(a[1]), "r"(a[2]), "r"(a[3]),
          "r"(b[0]), "r"(b[1]),
          "f"(c[0]), "f"(c[1]), "f"(c[2]), "f"(c[3]));
}
__device__ __forceinline__ void cp_async16(float* smem, const float* gmem) {
    unsigned saddr = (unsigned)__cvta_generic_to_shared(smem);
    asm volatile("cp.async.cg.shared.global [%0], [%1], 16;\n"
                 :: "r"(saddr), "l"(gmem) : "memory");
}
#define CP_COMMIT() asm volatile("cp.async.commit_group;\n" ::: "memory")
#define CP_WAIT(n)  asm volatile("cp.async.wait_group %0;\n" :: "n"(n) : "memory")

// ---------------------------------------------------------------------------
// GEMM: 128x128 block, 8 warps (4x2 of 32x64 warp tiles), 256 threads,
// K-step 32, 3-stage cp.async pipeline, consumer-side tf32 cvt.
// __launch_bounds__(256,2): 2 CTAs/SM -> 16 warps/SM.
// ---------------------------------------------------------------------------
#define GA_LD 36
#define GB_LD 132
#define AS_ST (128*GA_LD)
#define BS_ST (32*GB_LD)
#define G_STAGE (AS_ST + BS_ST)

template<int LDN>
__device__ __forceinline__ void gemm_stage(float* smg, const float* A,
    const float* Wm, int m0, int n0, int ks, int tid)
{
    float* As = smg + (ks % 3) * G_STAGE;
    float* Bs = As + AS_ST;
    const int k0 = ks << 5;
#pragma unroll
    for (int i = 0; i < 4; i++) {            // A tile 128x32 (1024 f4 / 256 thr)
        int id = i*256 + tid;
        int r = id >> 3, cc = (id & 7) << 2;
        cp_async16(&As[r*GA_LD + cc], A + (size_t)(m0 + r)*C_ + k0 + cc);
    }
#pragma unroll
    for (int i = 0; i < 4; i++) {            // B tile 32x128
        int id = i*256 + tid;
        int r = id >> 5, cc = (id & 31) << 2;
        cp_async16(&Bs[r*GB_LD + cc], Wm + (size_t)(k0 + r)*LDN + n0 + cc);
    }
    CP_COMMIT();
}

template<int LDN, bool SCATTER>
__global__ __launch_bounds__(256, 2) void mma_gemm(
    const float* __restrict__ A, const float* __restrict__ Wm,
    const float* __restrict__ bias, float* __restrict__ out)
{
    extern __shared__ float smg[];

    const int tid  = threadIdx.x;
    const int lane = tid & 31, w = tid >> 5;
    const int g = lane >> 2, ctg = lane & 3;
    const int wm = (w >> 1) << 5;     // 0,32,64,96
    const int wn = (w & 1)  << 6;     // 0,64
    const int m0 = blockIdx.y << 7, n0 = blockIdx.x << 7;

    float acc[2][8][4];
#pragma unroll
    for (int mt = 0; mt < 2; mt++)
#pragma unroll
        for (int nf = 0; nf < 8; nf++)
#pragma unroll
            for (int r = 0; r < 4; r++) acc[mt][nf][r] = 0.f;

    gemm_stage<LDN>(smg, A, Wm, m0, n0, 0, tid);
    gemm_stage<LDN>(smg, A, Wm, m0, n0, 1, tid);

#pragma unroll 1
    for (int ks = 0; ks < 32; ks++) {
        if (ks + 1 < 32) { CP_WAIT(1); } else { CP_WAIT(0); }
        __syncthreads();
        if (ks + 2 < 32) gemm_stage<LDN>(smg, A, Wm, m0, n0, ks + 2, tid);

        const float* As = smg + (ks % 3) * G_STAGE;
        const float* Bs = As + AS_ST;
#pragma unroll
        for (int kk = 0; kk < 4; kk++) {
            unsigned afr[2][4];
#pragma unroll
            for (int mt = 0; mt < 2; mt++) {
                int rb = wm + (mt << 4);
                afr[mt][0] = f2tf(As[(rb+g  )*GA_LD + (kk<<3) + ctg    ]);
                afr[mt][1] = f2tf(As[(rb+g+8)*GA_LD + (kk<<3) + ctg    ]);
                afr[mt][2] = f2tf(As[(rb+g  )*GA_LD + (kk<<3) + ctg + 4]);
                afr[mt][3] = f2tf(As[(rb+g+8)*GA_LD + (kk<<3) + ctg + 4]);
            }
#pragma unroll
            for (int nf = 0; nf < 8; nf++) {
                unsigned bfr[2];
                bfr[0] = f2tf(Bs[((kk<<3)+ctg  )*GB_LD + wn + (nf<<3) + g]);
                bfr[1] = f2tf(Bs[((kk<<3)+ctg+4)*GB_LD + wn + (nf<<3) + g]);
                mma_tf32(acc[0][nf], afr[0], bfr, acc[0][nf]);
                mma_tf32(acc[1][nf], afr[1], bfr, acc[1][nf]);
            }
        }
    }

    // Epilogue
#pragma unroll
    for (int mt = 0; mt < 2; mt++) {
#pragma unroll
        for (int nf = 0; nf < 8; nf++) {
            int col = n0 + wn + (nf << 3) + (ctg << 1);
            int r0  = m0 + wm + (mt << 4) + g;
            float b0 = bias[col], b1 = bias[col + 1];
            float2 v0 = make_float2(acc[mt][nf][0] + b0, acc[mt][nf][1] + b1);
            float2 v1 = make_float2(acc[mt][nf][2] + b0, acc[mt][nf][3] + b1);
            if (SCATTER) {
                int sect = col >> 10, cc = col & 1023;
                int h = cc >> 6, dd = cc & 63;
                float* dst = (sect == 0) ? g_q : (sect == 1) ? g_k : g_v;
                int bb0 = r0 >> 11, t0 = r0 & (T_-1);
                int r1 = r0 + 8, bb1 = r1 >> 11, t1 = r1 & (T_-1);
                *(float2*)(dst + (((size_t)bb0*H_ + h)*T_ + t0)*D_ + dd) = v0;
                *(float2*)(dst + (((size_t)bb1*H_ + h)*T_ + t1)*D_ + dd) = v1;
            } else {
                *(float2*)(out + (size_t)r0*LDN + col) = v0;
                *(float2*)(out + (size_t)(r0+8)*LDN + col) = v1;
            }
        }
    }
}

// ---------------------------------------------------------------------------
// Causal flash attention: 8 warps x 16 q-rows = 128-row block, 256 threads.
// 3-stage cp.async K/V ring; per-warp causal tile skip; exp2 softmax;
// P per-warp smem (syncwarp only). Q A-fragments resident in registers.
// ---------------------------------------------------------------------------
#define AK_LD 68
#define AV_LD 72
#define KS_SZ (64*AK_LD)
#define VS_SZ (64*AV_LD)
#define A_STAGE (KS_SZ + VS_SZ)
#define P_LD 68

__device__ __forceinline__ void attn_stage(float* sm, const float* Kg,
                                           const float* Vg, int kt, int tid)
{
    float* Ks = sm + (kt % 3) * A_STAGE;
    float* Vs = Ks + KS_SZ;
    const float* Kt = Kg + (size_t)(kt << 6) * D_;
    const float* Vt = Vg + (size_t)(kt << 6) * D_;
#pragma unroll
    for (int i = 0; i < 4; i++) {            // 64x64 tile: 1024 f4 / 256 thr / 2 arrays
        int id = i*256 + tid;
        int r = id >> 4, cc = (id & 15) << 2;
        cp_async16(&Ks[r*AK_LD + cc], Kt + r*D_ + cc);
        cp_async16(&Vs[r*AV_LD + cc], Vt + r*D_ + cc);
    }
    CP_COMMIT();
}

__global__ __launch_bounds__(256) void attn_mma()
{
    extern __shared__ float sm[];
    float* Ps = sm + 3*A_STAGE;          // per warp [16][P_LD]

    const int tid  = threadIdx.x;
    const int lane = tid & 31, w = tid >> 5;
    const int g = lane >> 2, ctg = lane & 3;
    const int qb = (gridDim.x - 1) - blockIdx.x;   // heavy blocks first
    const int bh = blockIdx.y;
    const int q0 = qb << 7;
    const int wq = q0 + (w << 4);                  // warp's 16 rows
    float* Pw = Ps + w * 16 * P_LD;

    const float* Qg = g_q + (size_t)bh * T_ * D_;
    const float* Kg = g_k + (size_t)bh * T_ * D_;
    const float* Vg = g_v + (size_t)bh * T_ * D_;

    // Q A-fragments; scale = 1/sqrt(64) * log2(e)  (exp2-domain softmax)
    const float qsc = 0.125f * 1.4426950408889634f;
    unsigned aq[8][4];
#pragma unroll
    for (int j = 0; j < 8; j++) {
        aq[j][0] = f2tf(Qg[(wq+g  )*D_ + (j<<3) + ctg    ] * qsc);
        aq[j][1] = f2tf(Qg[(wq+g+8)*D_ + (j<<3) + ctg    ] * qsc);
        aq[j][2] = f2tf(Qg[(wq+g  )*D_ + (j<<3) + ctg + 4] * qsc);
        aq[j][3] = f2tf(Qg[(wq+g+8)*D_ + (j<<3) + ctg + 4] * qsc);
    }

    float m_i[2] = {-1e30f, -1e30f};
    float l_i[2] = {0.f, 0.f};
    float o[8][4];
#pragma unroll
    for (int nf = 0; nf < 8; nf++)
#pragma unroll
        for (int r = 0; r < 4; r++) o[nf][r] = 0.f;

    const int nkt = (q0 >> 6) + 2;
    attn_stage(sm, Kg, Vg, 0, tid);
    attn_stage(sm, Kg, Vg, 1, tid);

#pragma unroll 1
    for (int kt = 0; kt < nkt; kt++) {
        if (kt + 1 < nkt) { CP_WAIT(1); } else { CP_WAIT(0); }
        __syncthreads();
        if (kt + 2 < nkt) attn_stage(sm, Kg, Vg, kt + 2, tid);

        if ((kt << 6) <= wq + 15) {      // per-warp causal tile skip
            const float* Ksb = sm + (kt % 3) * A_STAGE;
            const float* Vsb = Ksb + KS_SZ;

            // S = Q K^T
            float s[8][4];
#pragma unroll
            for (int nf = 0; nf < 8; nf++)
#pragma unroll
                for (int r = 0; r < 4; r++) s[nf][r] = 0.f;
#pragma unroll
            for (int kk = 0; kk < 8; kk++) {
#pragma unroll
                for (int nf = 0; nf < 8; nf++) {
                    unsigned bk[2];
                    bk[0] = f2tf(Ksb[((nf<<3)+g)*AK_LD + (kk<<3) + ctg    ]);
                    bk[1] = f2tf(Ksb[((nf<<3)+g)*AK_LD + (kk<<3) + ctg + 4]);
                    mma_tf32(s[nf], aq[kk], bk, s[nf]);
                }
            }

            // causal mask (diagonal-overlapping tiles only)
            if ((kt << 6) + 63 > wq) {
#pragma unroll
                for (int nf = 0; nf < 8; nf++) {
                    int col = (kt << 6) + (nf << 3) + (ctg << 1);
                    int r0 = wq + g, r1 = wq + g + 8;
                    if (col     > r0) s[nf][0] = -1e30f;
                    if (col + 1 > r0) s[nf][1] = -1e30f;
                    if (col     > r1) s[nf][2] = -1e30f;
                    if (col + 1 > r1) s[nf][3] = -1e30f;
                }
            }

            // online softmax (exp2 domain); a row lives on lanes 4g..4g+3
#pragma unroll
            for (int rr = 0; rr < 2; rr++) {
                float mx = -1e30f;
#pragma unroll
                for (int nf = 0; nf < 8; nf++)
                    mx = fmaxf(mx, fmaxf(s[nf][rr*2], s[nf][rr*2+1]));
                mx = fmaxf(mx, __shfl_xor_sync(0xffffffffu, mx, 1));
                mx = fmaxf(mx, __shfl_xor_sync(0xffffffffu, mx, 2));
                float mn = fmaxf(m_i[rr], mx);
                float alpha = exp2f(m_i[rr] - mn);
                m_i[rr] = mn;
                float rs = 0.f;
#pragma unroll
                for (int nf = 0; nf < 8; nf++) {
                    float p0 = exp2f(s[nf][rr*2]   - mn);
                    float p1 = exp2f(s[nf][rr*2+1] - mn);
                    s[nf][rr*2] = p0; s[nf][rr*2+1] = p1;
                    rs += p0 + p1;
                }
                rs += __shfl_xor_sync(0xffffffffu, rs, 1);
                rs += __shfl_xor_sync(0xffffffffu, rs, 2);
                l_i[rr] = l_i[rr]*alpha + rs;
#pragma unroll
                for (int nf = 0; nf < 8; nf++) {
                    o[nf][rr*2]   *= alpha;
                    o[nf][rr*2+1] *= alpha;
                }
            }

            // P -> per-warp smem (tf32-rounded)
#pragma unroll
            for (int nf = 0; nf < 8; nf++) {
                *(float2*)&Pw[ g    *P_LD + (nf<<3) + (ctg<<1)] =
                    make_float2(f2tf_f(s[nf][0]), f2tf_f(s[nf][1]));
                *(float2*)&Pw[(g+8) *P_LD + (nf<<3) + (ctg<<1)] =
                    make_float2(f2tf_f(s[nf][2]), f2tf_f(s[nf][3]));
            }
            __syncwarp();

            // O += P @ V
#pragma unroll
            for (int kk = 0; kk < 8; kk++) {
                unsigned ap[4];
                ap[0] = __float_as_uint(Pw[ g    *P_LD + (kk<<3) + ctg    ]);
                ap[1] = __float_as_uint(Pw[(g+8) *P_LD + (kk<<3) + ctg    ]);
                ap[2] = __float_as_uint(Pw[ g    *P_LD + (kk<<3) + ctg + 4]);
                ap[3] = __float_as_uint(Pw[(g+8) *P_LD + (kk<<3) + ctg + 4]);
#pragma unroll
                for (int nf = 0; nf < 8; nf++) {
                    unsigned bv[2];
                    bv[0] = f2tf(Vsb[((kk<<3)+ctg  )*AV_LD + (nf<<3) + g]);
                    bv[1] = f2tf(Vsb[((kk<<3)+ctg+4)*AV_LD + (nf<<3) + g]);
                    mma_tf32(o[nf], ap, bv, o[nf]);
                }
            }
        }
    }

    // epilogue: write [B*T, C]
    const int b = bh >> 4, h = bh & 15;
    float inv0 = 1.0f / l_i[0], inv1 = 1.0f / l_i[1];
#pragma unroll
    for (int nf = 0; nf < 8; nf++) {
        int dd = (nf << 3) + (ctg << 1);
        size_t base0 = (size_t)(b*T_ + wq + g    )*C_ + (h << 6) + dd;
        size_t base1 = (size_t)(b*T_ + wq + g + 8)*C_ + (h << 6) + dd;
        *(float2*)(g_ao + base0) = make_float2(o[nf][0]*inv0, o[nf][1]*inv0);
        *(float2*)(g_ao + base1) = make_float2(o[nf][2]*inv1, o[nf][3]*inv1);
    }
}

// ---------------------------------------------------------------------------
extern "C" void kernel_launch(void* const* d_in, const int* in_sizes, int n_in,
                              void* d_out, int out_size)
{
    const float* x      = (const float*)d_in[0];
    const float* w_qkv  = (const float*)d_in[1];
    const float* b_qkv  = (const float*)d_in[2];
    const float* w_proj = (const float*)d_in[3];
    const float* b_proj = (const float*)d_in[4];
    float* out = (float*)d_out;

    float* ao_ptr = nullptr;
    cudaGetSymbolAddress((void**)&ao_ptr, g_ao);

    const int gemm_smem = 3 * G_STAGE * (int)sizeof(float);                 // 105984
    const int attn_smem = (3*A_STAGE + 8*16*P_LD) * (int)sizeof(float);     // 142336

    cudaFuncSetAttribute(mma_gemm<3*C_, true>,
                         cudaFuncAttributeMaxDynamicSharedMemorySize, gemm_smem);
    cudaFuncSetAttribute(mma_gemm<C_, false>,
                         cudaFuncAttributeMaxDynamicSharedMemorySize, gemm_smem);
    cudaFuncSetAttribute(attn_mma,
                         cudaFuncAttributeMaxDynamicSharedMemorySize, attn_smem);

    dim3 gq(24, 64);   // N=3072/128, M=8192/128
    mma_gemm<3*C_, true><<<gq, 256, gemm_smem>>>(x, w_qkv, b_qkv, nullptr);

    dim3 ga(16, 64);   // q-blocks (128 rows), B*H
    attn_mma<<<ga, 256, attn_smem>>>();

    dim3 gp(8, 64);    // N=1024/128, M=8192/128
    mma_gemm<C_, false><<<gp, 256, gemm_smem>>>(ao_ptr, w_proj, b_proj, out);
}

// round 6
// speedup vs baseline: 1.1680x; 1.1138x over previous
#include <cuda_runtime.h>

#define B_ 4
#define T_ 2048
#define C_ 1024
#define H_ 16
#define D_ 64
#define M_ (B_*T_)

// Scratch (device globals; allocation-free per harness rules)
__device__ float g_x [M_*C_];         // x, tf32-rounded, k-interleaved per 8
__device__ float g_wq[3*C_*C_];       // w_qkv^T: [n][k], tf32, k-interleaved
__device__ float g_wp[C_*C_];         // w_proj^T: [n][k], tf32, k-interleaved
__device__ float g_q [B_*H_*T_*D_];   // [B,H,T,d], tf32-rounded
__device__ float g_k [B_*H_*T_*D_];
__device__ float g_v [B_*H_*T_*D_];
__device__ float g_ao[M_*C_];         // attn out, [B*T,C], tf32, k-interleaved

// ---------------------------------------------------------------------------
// helpers
// ---------------------------------------------------------------------------
__device__ __forceinline__ unsigned f2tf(float x) {
    unsigned r;
    asm("cvt.rna.tf32.f32 %0, %1;" : "=r"(r) : "f"(x));
    return r;
}
__device__ __forceinline__ float f2tf_f(float x) {
    return __uint_as_float(f2tf(x));
}
__device__ __forceinline__ void mma_tf32(float* d, const unsigned* a,
                                         const unsigned* b, const float* c) {
    asm volatile(
        "mma.sync.aligned.m16n8k8.row.col.f32.tf32.tf32.f32 "
        "{%0,%1,%2,%3}, {%4,%5,%6,%7}, {%8,%9}, {%10,%11,%12,%13};\n"
        : "=f"(d[0]), "=f"(d[1]), "=f"(d[2]), "=f"(d[3])
        : "r"(a[0]), "r"(a[1]), "r"(a[2]), "r"(a[3]),
          "r"(b[0]), "r"(b[1]),
          "f"(c[0]), "f"(c[1]), "f"(c[2]), "f"(c[3]));
}
__device__ __forceinline__ void cp_async16(float* smem, const float* gmem) {
    unsigned saddr = (unsigned)__cvta_generic_to_shared(smem);
    asm volatile("cp.async.cg.shared.global [%0], [%1], 16;\n"
                 :: "r"(saddr), "l"(gmem) : "memory");
}
#define CP_COMMIT() asm volatile("cp.async.commit_group;\n" ::: "memory")
#define CP_WAIT(n)  asm volatile("cp.async.wait_group %0;\n" :: "n"(n) : "memory")

// ---------------------------------------------------------------------------
// Prepack kernels (one-time, memory-bound).
// Interleave map within each 8-group of k:  j -> (j<4) ? 2j : 2(j-4)+1
// so fragment pairs (k, k+4) become adjacent -> LDS.64 in GEMM hot loop.
// ---------------------------------------------------------------------------
__global__ __launch_bounds__(256) void pack_rows(const float* __restrict__ in,
                                                 float* __restrict__ out)
{
    size_t gid = (size_t)blockIdx.x * 256 + threadIdx.x;   // one 8-group each
    const float4 a = *(const float4*)(in + gid*8);
    const float4 b = *(const float4*)(in + gid*8 + 4);
    float4 o0 = make_float4(f2tf_f(a.x), f2tf_f(b.x), f2tf_f(a.y), f2tf_f(b.y));
    float4 o1 = make_float4(f2tf_f(a.z), f2tf_f(b.z), f2tf_f(a.w), f2tf_f(b.w));
    *(float4*)(out + gid*8)     = o0;
    *(float4*)(out + gid*8 + 4) = o1;
}

// W [K=1024][N] row-major  ->  out [N][1024] transposed + rounded + interleaved
__global__ __launch_bounds__(256) void pack_wt(const float* __restrict__ W,
                                               float* __restrict__ out, int N)
{
    __shared__ float t[32][33];
    const int n0 = blockIdx.x << 5, k0 = blockIdx.y << 5;
    const int tx = threadIdx.x, ty = threadIdx.y;          // 32 x 8
#pragma unroll
    for (int i = ty; i < 32; i += 8)
        t[i][tx] = W[(size_t)(k0 + i) * N + n0 + tx];
    __syncthreads();
    const int j = tx & 7, grp = tx >> 3;
    const int kp = (grp << 3) + ((j < 4) ? (j << 1) : (((j - 4) << 1) + 1));
#pragma unroll
    for (int i = ty; i < 32; i += 8)
        out[(size_t)(n0 + i) * C_ + k0 + kp] = f2tf_f(t[tx][i]);
}

// ---------------------------------------------------------------------------
// GEMM: 128x128 block, 8 warps (4x2 of 32x64 warp tiles), 256 threads.
// A [m][k] and B [n][k] both packed (tf32 + interleaved), stride C_.
// 2-stage cp.async; inner loop: 12 LDS.64 + 16 MMA per kk, zero cvt.
// ---------------------------------------------------------------------------
#define G_LD 40
#define G_TILE (128*G_LD)
#define G_STAGE (2*G_TILE)

__device__ __forceinline__ void gemm_stage(float* smg, const float* Ap,
    const float* Bp, int m0, int n0, int ks, int tid)
{
    float* As = smg + (ks & 1) * G_STAGE;
    float* Bs = As + G_TILE;
    const int k0 = ks << 5;
    const int r = tid >> 3, c = (tid & 7) << 2;
#pragma unroll
    for (int i = 0; i < 4; i++) {      // 128x32 tile = 1024 f4 / 256 thr
        cp_async16(&As[(i*32 + r)*G_LD + c], Ap + (size_t)(m0 + i*32 + r)*C_ + k0 + c);
        cp_async16(&Bs[(i*32 + r)*G_LD + c], Bp + (size_t)(n0 + i*32 + r)*C_ + k0 + c);
    }
    CP_COMMIT();
}

template<bool SCATTER>
__global__ __launch_bounds__(256, 2) void mma_gemm(
    const float* __restrict__ Ap, const float* __restrict__ Bp,
    const float* __restrict__ bias, float* __restrict__ out)
{
    extern __shared__ float smg[];

    const int tid  = threadIdx.x;
    const int lane = tid & 31, w = tid >> 5;
    const int g = lane >> 2, ctg = lane & 3;
    const int wm = (w >> 1) << 5;     // 0,32,64,96
    const int wn = (w & 1)  << 6;     // 0,64
    const int m0 = blockIdx.y << 7, n0 = blockIdx.x << 7;

    float acc[2][8][4];
#pragma unroll
    for (int mt = 0; mt < 2; mt++)
#pragma unroll
        for (int nf = 0; nf < 8; nf++)
#pragma unroll
            for (int r = 0; r < 4; r++) acc[mt][nf][r] = 0.f;

    gemm_stage(smg, Ap, Bp, m0, n0, 0, tid);

#pragma unroll 1
    for (int ks = 0; ks < 32; ks++) {
        CP_WAIT(0);
        __syncthreads();
        if (ks + 1 < 32) gemm_stage(smg, Ap, Bp, m0, n0, ks + 1, tid);

        const float* As = smg + (ks & 1) * G_STAGE;
        const float* Bs = As + G_TILE;
#pragma unroll
        for (int kk = 0; kk < 4; kk++) {
            unsigned afr[2][4];
#pragma unroll
            for (int mt = 0; mt < 2; mt++) {
                int rb = wm + (mt << 4) + g;
                float2 v0 = *(const float2*)&As[(rb  )*G_LD + (kk<<3) + (ctg<<1)];
                float2 v1 = *(const float2*)&As[(rb+8)*G_LD + (kk<<3) + (ctg<<1)];
                afr[mt][0] = __float_as_uint(v0.x);
                afr[mt][2] = __float_as_uint(v0.y);
                afr[mt][1] = __float_as_uint(v1.x);
                afr[mt][3] = __float_as_uint(v1.y);
            }
#pragma unroll
            for (int nf = 0; nf < 8; nf++) {
                float2 bv = *(const float2*)&Bs[(wn + (nf<<3) + g)*G_LD + (kk<<3) + (ctg<<1)];
                unsigned bfr[2] = { __float_as_uint(bv.x), __float_as_uint(bv.y) };
                mma_tf32(acc[0][nf], afr[0], bfr, acc[0][nf]);
                mma_tf32(acc[1][nf], afr[1], bfr, acc[1][nf]);
            }
        }
    }

    // Epilogue
#pragma unroll
    for (int mt = 0; mt < 2; mt++) {
#pragma unroll
        for (int nf = 0; nf < 8; nf++) {
            int col = n0 + wn + (nf << 3) + (ctg << 1);
            int r0  = m0 + wm + (mt << 4) + g;
            float b0 = bias[col], b1 = bias[col + 1];
            if (SCATTER) {   // qkv -> g_q/g_k/g_v, tf32-rounded
                int sect = col >> 10, cc = col & 1023;
                int h = cc >> 6, dd = cc & 63;
                float* dst = (sect == 0) ? g_q : (sect == 1) ? g_k : g_v;
                float2 v0 = make_float2(f2tf_f(acc[mt][nf][0] + b0),
                                        f2tf_f(acc[mt][nf][1] + b1));
                float2 v1 = make_float2(f2tf_f(acc[mt][nf][2] + b0),
                                        f2tf_f(acc[mt][nf][3] + b1));
                int bb0 = r0 >> 11, t0 = r0 & (T_-1);
                int r1 = r0 + 8, bb1 = r1 >> 11, t1 = r1 & (T_-1);
                *(float2*)(dst + (((size_t)bb0*H_ + h)*T_ + t0)*D_ + dd) = v0;
                *(float2*)(dst + (((size_t)bb1*H_ + h)*T_ + t1)*D_ + dd) = v1;
            } else {         // final output: plain f32
                float2 v0 = make_float2(acc[mt][nf][0] + b0, acc[mt][nf][1] + b1);
                float2 v1 = make_float2(acc[mt][nf][2] + b0, acc[mt][nf][3] + b1);
                *(float2*)(out + (size_t)r0*C_ + col) = v0;
                *(float2*)(out + (size_t)(r0+8)*C_ + col) = v1;
            }
        }
    }
}

// ---------------------------------------------------------------------------
// Causal flash attention: 8 warps x 16 q-rows = 128-row block, 256 threads.
// 2-stage cp.async K/V ring (K/V pre-rounded -> raw-bit LDS, zero cvt);
// per-warp causal tile skip; exp2 softmax; P per-warp (syncwarp only).
// Epilogue writes g_ao tf32-rounded + k-interleaved for the packed proj GEMM.
// ---------------------------------------------------------------------------
#define AK_LD 68
#define AV_LD 72
#define KS_SZ (64*AK_LD)
#define VS_SZ (64*AV_LD)
#define A_STAGE (KS_SZ + VS_SZ)
#define P_LD 68

__device__ __forceinline__ void attn_stage(float* sm, const float* Kg,
                                           const float* Vg, int kt, int tid)
{
    float* Ks = sm + (kt & 1) * A_STAGE;
    float* Vs = Ks + KS_SZ;
    const float* Kt = Kg + (size_t)(kt << 6) * D_;
    const float* Vt = Vg + (size_t)(kt << 6) * D_;
    const int r = tid >> 4, c = (tid & 15) << 2;
#pragma unroll
    for (int i = 0; i < 4; i++) {
        cp_async16(&Ks[(i*16 + r)*AK_LD + c], Kt + (i*16 + r)*D_ + c);
        cp_async16(&Vs[(i*16 + r)*AV_LD + c], Vt + (i*16 + r)*D_ + c);
    }
    CP_COMMIT();
}

__global__ __launch_bounds__(256, 2) void attn_mma()
{
    extern __shared__ float sm[];
    float* Ps = sm + 2*A_STAGE;          // per warp [16][P_LD]

    const int tid  = threadIdx.x;
    const int lane = tid & 31, w = tid >> 5;
    const int g = lane >> 2, ctg = lane & 3;
    const int qb = (gridDim.x - 1) - blockIdx.x;   // heavy blocks first
    const int bh = blockIdx.y;
    const int q0 = qb << 7;
    const int wq = q0 + (w << 4);                  // warp's 16 rows
    float* Pw = Ps + w * 16 * P_LD;

    const float* Qg = g_q + (size_t)bh * T_ * D_;
    const float* Kg = g_k + (size_t)bh * T_ * D_;
    const float* Vg = g_v + (size_t)bh * T_ * D_;

    // Q A-fragments; scale = 1/sqrt(64) * log2(e)  (exp2-domain softmax)
    const float qsc = 0.125f * 1.4426950408889634f;
    unsigned aq[8][4];
#pragma unroll
    for (int j = 0; j < 8; j++) {
        aq[j][0] = f2tf(Qg[(wq+g  )*D_ + (j<<3) + ctg    ] * qsc);
        aq[j][1] = f2tf(Qg[(wq+g+8)*D_ + (j<<3) + ctg    ] * qsc);
        aq[j][2] = f2tf(Qg[(wq+g  )*D_ + (j<<3) + ctg + 4] * qsc);
        aq[j][3] = f2tf(Qg[(wq+g+8)*D_ + (j<<3) + ctg + 4] * qsc);
    }

    float m_i[2] = {-1e30f, -1e30f};
    float l_i[2] = {0.f, 0.f};
    float o[8][4];
#pragma unroll
    for (int nf = 0; nf < 8; nf++)
#pragma unroll
        for (int r = 0; r < 4; r++) o[nf][r] = 0.f;

    const int nkt = (q0 >> 6) + 2;
    attn_stage(sm, Kg, Vg, 0, tid);

#pragma unroll 1
    for (int kt = 0; kt < nkt; kt++) {
        CP_WAIT(0);
        __syncthreads();
        if (kt + 1 < nkt) attn_stage(sm, Kg, Vg, kt + 1, tid);

        if ((kt << 6) <= wq + 15) {      // per-warp causal tile skip
            const float* Ksb = sm + (kt & 1) * A_STAGE;
            const float* Vsb = Ksb + KS_SZ;

            // S = Q K^T  (K pre-rounded -> raw bits)
            float s[8][4];
#pragma unroll
            for (int nf = 0; nf < 8; nf++)
#pragma unroll
                for (int r = 0; r < 4; r++) s[nf][r] = 0.f;
#pragma unroll
            for (int kk = 0; kk < 8; kk++) {
#pragma unroll
                for (int nf = 0; nf < 8; nf++) {
                    unsigned bk[2];
                    bk[0] = __float_as_uint(Ksb[((nf<<3)+g)*AK_LD + (kk<<3) + ctg    ]);
                    bk[1] = __float_as_uint(Ksb[((nf<<3)+g)*AK_LD + (kk<<3) + ctg + 4]);
                    mma_tf32(s[nf], aq[kk], bk, s[nf]);
                }
            }

            // causal mask (diagonal-overlapping tiles only)
            if ((kt << 6) + 63 > wq) {
#pragma unroll
                for (int nf = 0; nf < 8; nf++) {
                    int col = (kt << 6) + (nf << 3) + (ctg << 1);
                    int r0 = wq + g, r1 = wq + g + 8;
                    if (col     > r0) s[nf][0] = -1e30f;
                    if (col + 1 > r0) s[nf][1] = -1e30f;
                    if (col     > r1) s[nf][2] = -1e30f;
                    if (col + 1 > r1) s[nf][3] = -1e30f;
                }
            }

            // online softmax (exp2 domain); a row lives on lanes 4g..4g+3
#pragma unroll
            for (int rr = 0; rr < 2; rr++) {
                float mx = -1e30f;
#pragma unroll
                for (int nf = 0; nf < 8; nf++)
                    mx = fmaxf(mx, fmaxf(s[nf][rr*2], s[nf][rr*2+1]));
                mx = fmaxf(mx, __shfl_xor_sync(0xffffffffu, mx, 1));
                mx = fmaxf(mx, __shfl_xor_sync(0xffffffffu, mx, 2));
                float mn = fmaxf(m_i[rr], mx);
                float alpha = exp2f(m_i[rr] - mn);
                m_i[rr] = mn;
                float rs = 0.f;
#pragma unroll
                for (int nf = 0; nf < 8; nf++) {
                    float p0 = exp2f(s[nf][rr*2]   - mn);
                    float p1 = exp2f(s[nf][rr*2+1] - mn);
                    s[nf][rr*2] = p0; s[nf][rr*2+1] = p1;
                    rs += p0 + p1;
                }
                rs += __shfl_xor_sync(0xffffffffu, rs, 1);
                rs += __shfl_xor_sync(0xffffffffu, rs, 2);
                l_i[rr] = l_i[rr]*alpha + rs;
#pragma unroll
                for (int nf = 0; nf < 8; nf++) {
                    o[nf][rr*2]   *= alpha;
                    o[nf][rr*2+1] *= alpha;
                }
            }

            // P -> per-warp smem (tf32-rounded)
#pragma unroll
            for (int nf = 0; nf < 8; nf++) {
                *(float2*)&Pw[ g    *P_LD + (nf<<3) + (ctg<<1)] =
                    make_float2(f2tf_f(s[nf][0]), f2tf_f(s[nf][1]));
                *(float2*)&Pw[(g+8) *P_LD + (nf<<3) + (ctg<<1)] =
                    make_float2(f2tf_f(s[nf][2]), f2tf_f(s[nf][3]));
            }
            __syncwarp();

            // O += P @ V  (V pre-rounded -> raw bits)
#pragma unroll
            for (int kk = 0; kk < 8; kk++) {
                unsigned ap[4];
                ap[0] = __float_as_uint(Pw[ g    *P_LD + (kk<<3) + ctg    ]);
                ap[1] = __float_as_uint(Pw[(g+8) *P_LD + (kk<<3) + ctg    ]);
                ap[2] = __float_as_uint(Pw[ g    *P_LD + (kk<<3) + ctg + 4]);
                ap[3] = __float_as_uint(Pw[(g+8) *P_LD + (kk<<3) + ctg + 4]);
#pragma unroll
                for (int nf = 0; nf < 8; nf++) {
                    unsigned bv[2];
                    bv[0] = __float_as_uint(Vsb[((kk<<3)+ctg  )*AV_LD + (nf<<3) + g]);
                    bv[1] = __float_as_uint(Vsb[((kk<<3)+ctg+4)*AV_LD + (nf<<3) + g]);
                    mma_tf32(o[nf], ap, bv, o[nf]);
                }
            }
        }
    }

    // epilogue: write [B*T, C] rounded + k-interleaved (packed proj input).
    // col j within its 8-group = 2*ctg (even), 2*ctg+1 (odd):
    //   p0 = interleave(2*ctg) = ((ctg&1)<<2) + (ctg>>1);  p1 = p0 + 2
    const int b = bh >> 4, h = bh & 15;
    const int p0 = ((ctg & 1) << 2) + (ctg >> 1), p1 = p0 + 2;
    float inv0 = 1.0f / l_i[0], inv1 = 1.0f / l_i[1];
#pragma unroll
    for (int nf = 0; nf < 8; nf++) {
        size_t base0 = (size_t)(b*T_ + wq + g    )*C_ + (h << 6) + (nf << 3);
        size_t base1 = (size_t)(b*T_ + wq + g + 8)*C_ + (h << 6) + (nf << 3);
        g_ao[base0 + p0] = f2tf_f(o[nf][0]*inv0);
        g_ao[base0 + p1] = f2tf_f(o[nf][1]*inv0);
        g_ao[base1 + p0] = f2tf_f(o[nf][2]*inv1);
        g_ao[base1 + p1] = f2tf_f(o[nf][3]*inv1);
    }
}

// ---------------------------------------------------------------------------
extern "C" void kernel_launch(void* const* d_in, const int* in_sizes, int n_in,
                              void* d_out, int out_size)
{
    const float* x      = (const float*)d_in[0];
    const float* w_qkv  = (const float*)d_in[1];
    const float* b_qkv  = (const float*)d_in[2];
    const float* w_proj = (const float*)d_in[3];
    const float* b_proj = (const float*)d_in[4];
    float* out = (float*)d_out;

    float *x_p, *wq_p, *wp_p, *ao_p;
    cudaGetSymbolAddress((void**)&x_p,  g_x);
    cudaGetSymbolAddress((void**)&wq_p, g_wq);
    cudaGetSymbolAddress((void**)&wp_p, g_wp);
    cudaGetSymbolAddress((void**)&ao_p, g_ao);

    const int gemm_smem = 2 * G_STAGE * (int)sizeof(float);               // 81920
    const int attn_smem = (2*A_STAGE + 8*16*P_LD) * (int)sizeof(float);   // 106496

    cudaFuncSetAttribute(mma_gemm<true>,
                         cudaFuncAttributeMaxDynamicSharedMemorySize, gemm_smem);
    cudaFuncSetAttribute(mma_gemm<false>,
                         cudaFuncAttributeMaxDynamicSharedMemorySize, gemm_smem);
    cudaFuncSetAttribute(attn_mma,
                         cudaFuncAttributeMaxDynamicSharedMemorySize, attn_smem);

    // prepack (one-time per call; memory-bound)
    pack_rows<<<M_*C_/8/256, 256>>>(x, x_p);
    pack_wt<<<dim3(3*C_/32, C_/32), dim3(32, 8)>>>(w_qkv, wq_p, 3*C_);
    pack_wt<<<dim3(C_/32, C_/32),   dim3(32, 8)>>>(w_proj, wp_p, C_);

    dim3 gq(24, 64);   // N=3072/128, M=8192/128
    mma_gemm<true><<<gq, 256, gemm_smem>>>(x_p, wq_p, b_qkv, nullptr);

    dim3 ga(16, 64);   // q-blocks (128 rows), B*H
    attn_mma<<<ga, 256, attn_smem>>>();

    dim3 gp(8, 64);    // N=1024/128, M=8192/128
    mma_gemm<false><<<gp, 256, gemm_smem>>>(ao_p, wp_p, b_proj, out);
}

// round 7
// speedup vs baseline: 1.2464x; 1.0671x over previous
#include <cuda_runtime.h>

#define B_ 4
#define T_ 2048
#define C_ 1024
#define H_ 16
#define D_ 64
#define M_ (B_*T_)

// Scratch (device globals; allocation-free per harness rules)
__device__ float g_x [M_*C_];         // x, tf32-rounded, k-interleaved per 8
__device__ float g_wq[3*C_*C_];       // w_qkv^T: [n][k], tf32, k-interleaved
__device__ float g_wp[C_*C_];         // w_proj^T: [n][k], tf32, k-interleaved
__device__ float g_q [B_*H_*T_*D_];   // [B,H,T,d], tf32, plain
__device__ float g_k [B_*H_*T_*D_];   // [B,H,T,d], tf32, d-interleaved per 8
__device__ float g_v [B_*H_*T_*D_];   // [B,H,T,d], tf32, plain
__device__ float g_ao[M_*C_];         // attn out, [B*T,C], tf32, k-interleaved

// ---------------------------------------------------------------------------
// helpers
// ---------------------------------------------------------------------------
__device__ __forceinline__ unsigned f2tf(float x) {
    unsigned r;
    asm("cvt.rna.tf32.f32 %0, %1;" : "=r"(r) : "f"(x));
    return r;
}
__device__ __forceinline__ float f2tf_f(float x) {
    return __uint_as_float(f2tf(x));
}
__device__ __forceinline__ void mma_tf32(float* d, const unsigned* a,
                                         const unsigned* b, const float* c) {
    asm volatile(
        "mma.sync.aligned.m16n8k8.row.col.f32.tf32.tf32.f32 "
        "{%0,%1,%2,%3}, {%4,%5,%6,%7}, {%8,%9}, {%10,%11,%12,%13};\n"
        : "=f"(d[0]), "=f"(d[1]), "=f"(d[2]), "=f"(d[3])
        : "r"(a[0]), "r"(a[1]), "r"(a[2]), "r"(a[3]),
          "r"(b[0]), "r"(b[1]),
          "f"(c[0]), "f"(c[1]), "f"(c[2]), "f"(c[3]));
}
__device__ __forceinline__ void cp_async16(float* smem, const float* gmem) {
    unsigned saddr = (unsigned)__cvta_generic_to_shared(smem);
    asm volatile("cp.async.cg.shared.global [%0], [%1], 16;\n"
                 :: "r"(saddr), "l"(gmem) : "memory");
}
#define CP_COMMIT() asm volatile("cp.async.commit_group;\n" ::: "memory")
#define CP_WAIT(n)  asm volatile("cp.async.wait_group %0;\n" :: "n"(n) : "memory")

// ---------------------------------------------------------------------------
// Prepack kernels (one-time, memory-bound).
// Interleave map within each 8-group of k:  j -> (j<4) ? 2j : 2(j-4)+1
// so fragment pairs (k, k+4) become adjacent -> LDS.64 in hot loops.
// ---------------------------------------------------------------------------
__global__ __launch_bounds__(256) void pack_rows(const float* __restrict__ in,
                                                 float* __restrict__ out)
{
    size_t gid = (size_t)blockIdx.x * 256 + threadIdx.x;   // one 8-group each
    const float4 a = *(const float4*)(in + gid*8);
    const float4 b = *(const float4*)(in + gid*8 + 4);
    float4 o0 = make_float4(f2tf_f(a.x), f2tf_f(b.x), f2tf_f(a.y), f2tf_f(b.y));
    float4 o1 = make_float4(f2tf_f(a.z), f2tf_f(b.z), f2tf_f(a.w), f2tf_f(b.w));
    *(float4*)(out + gid*8)     = o0;
    *(float4*)(out + gid*8 + 4) = o1;
}

// W [K=1024][N] row-major  ->  out [N][1024] transposed + rounded + interleaved
__global__ __launch_bounds__(256) void pack_wt(const float* __restrict__ W,
                                               float* __restrict__ out, int N)
{
    __shared__ float t[32][33];
    const int n0 = blockIdx.x << 5, k0 = blockIdx.y << 5;
    const int tx = threadIdx.x, ty = threadIdx.y;          // 32 x 8
#pragma unroll
    for (int i = ty; i < 32; i += 8)
        t[i][tx] = W[(size_t)(k0 + i) * N + n0 + tx];
    __syncthreads();
    const int j = tx & 7, grp = tx >> 3;
    const int kp = (grp << 3) + ((j < 4) ? (j << 1) : (((j - 4) << 1) + 1));
#pragma unroll
    for (int i = ty; i < 32; i += 8)
        out[(size_t)(n0 + i) * C_ + k0 + kp] = f2tf_f(t[tx][i]);
}

// ---------------------------------------------------------------------------
// GEMM: 128x128 block, 8 warps (4x2 of 32x64 warp tiles), 256 threads.
// A [m][k], B [n][k], both packed. Smem: LD=32, XOR swizzle
// word' = word ^ ((row&3)<<3)  ->  pad-free, conflict-free LDS.64.
// 3-stage cp.async ring, CP_WAIT(1): ~2 compute blocks of latency cover.
// ---------------------------------------------------------------------------
#define G_TILEW (128*32)
#define G_STAGEW (2*G_TILEW)

__device__ __forceinline__ void gemm_stage(float* smg, const float* Ap,
    const float* Bp, int m0, int n0, int ks, int st, int tid)
{
    float* As = smg + st * G_STAGEW;
    float* Bs = As + G_TILEW;
    const int k0 = ks << 5;
    const int r = tid >> 3, c = (tid & 7) << 2;
    const int cw = c ^ ((r & 3) << 3);           // swizzled chunk position
#pragma unroll
    for (int i = 0; i < 4; i++) {                // 128x32 tile = 1024 f4
        cp_async16(&As[(i*32 + r)*32 + cw], Ap + (size_t)(m0 + i*32 + r)*C_ + k0 + c);
        cp_async16(&Bs[(i*32 + r)*32 + cw], Bp + (size_t)(n0 + i*32 + r)*C_ + k0 + c);
    }
    CP_COMMIT();
}

template<bool SCATTER>
__global__ __launch_bounds__(256, 2) void mma_gemm(
    const float* __restrict__ Ap, const float* __restrict__ Bp,
    const float* __restrict__ bias, float* __restrict__ out)
{
    extern __shared__ float smg[];

    const int tid  = threadIdx.x;
    const int lane = tid & 31, w = tid >> 5;
    const int g = lane >> 2, ctg = lane & 3;
    const int msk = (g & 3) << 3;                // read-side swizzle mask
    const int wm = (w >> 1) << 5;     // 0,32,64,96
    const int wn = (w & 1)  << 6;     // 0,64
    const int m0 = blockIdx.y << 7, n0 = blockIdx.x << 7;

    float acc[2][8][4];
#pragma unroll
    for (int mt = 0; mt < 2; mt++)
#pragma unroll
        for (int nf = 0; nf < 8; nf++)
#pragma unroll
            for (int r = 0; r < 4; r++) acc[mt][nf][r] = 0.f;

    gemm_stage(smg, Ap, Bp, m0, n0, 0, 0, tid);
    gemm_stage(smg, Ap, Bp, m0, n0, 1, 1, tid);

    int st = 0, st2 = 2;                         // stage of ks, of ks+2
#pragma unroll 1
    for (int ks = 0; ks < 32; ks++) {
        CP_WAIT(1);
        __syncthreads();
        if (ks + 2 < 32) gemm_stage(smg, Ap, Bp, m0, n0, ks + 2, st2, tid);

        const float* As = smg + st * G_STAGEW;
        const float* Bs = As + G_TILEW;
#pragma unroll
        for (int kk = 0; kk < 4; kk++) {
            const int ca = ((kk << 3) ^ msk) + (ctg << 1);   // loop-invariant per kk
            unsigned afr[2][4];
#pragma unroll
            for (int mt = 0; mt < 2; mt++) {
                int rb = wm + (mt << 4) + g;
                float2 v0 = *(const float2*)&As[(rb  ) * 32 + ca];
                float2 v1 = *(const float2*)&As[(rb+8) * 32 + ca];
                afr[mt][0] = __float_as_uint(v0.x);
                afr[mt][2] = __float_as_uint(v0.y);
                afr[mt][1] = __float_as_uint(v1.x);
                afr[mt][3] = __float_as_uint(v1.y);
            }
#pragma unroll
            for (int nf = 0; nf < 8; nf++) {
                float2 bv = *(const float2*)&Bs[(wn + (nf<<3) + g) * 32 + ca];
                unsigned bfr[2] = { __float_as_uint(bv.x), __float_as_uint(bv.y) };
                mma_tf32(acc[0][nf], afr[0], bfr, acc[0][nf]);
                mma_tf32(acc[1][nf], afr[1], bfr, acc[1][nf]);
            }
        }
        st  = (st  == 2) ? 0 : st  + 1;
        st2 = (st2 == 2) ? 0 : st2 + 1;
    }

    // Epilogue
    const int p0 = ((ctg & 1) << 2) + (ctg >> 1), p1 = p0 + 2;  // interleave pos
#pragma unroll
    for (int mt = 0; mt < 2; mt++) {
#pragma unroll
        for (int nf = 0; nf < 8; nf++) {
            int col = n0 + wn + (nf << 3) + (ctg << 1);
            int r0  = m0 + wm + (mt << 4) + g;
            float b0 = bias[col], b1 = bias[col + 1];
            if (SCATTER) {   // qkv -> g_q/g_k/g_v, tf32-rounded
                int sect = col >> 10, cc = col & 1023;
                int h = cc >> 6, dd = cc & 63;
                float* dst = (sect == 0) ? g_q : (sect == 1) ? g_k : g_v;
                int bb0 = r0 >> 11, t0 = r0 & (T_-1);
                int r1 = r0 + 8, bb1 = r1 >> 11, t1 = r1 & (T_-1);
                size_t i0 = (((size_t)bb0*H_ + h)*T_ + t0)*D_;
                size_t i1 = (((size_t)bb1*H_ + h)*T_ + t1)*D_;
                float e00 = f2tf_f(acc[mt][nf][0] + b0);
                float e01 = f2tf_f(acc[mt][nf][1] + b1);
                float e10 = f2tf_f(acc[mt][nf][2] + b0);
                float e11 = f2tf_f(acc[mt][nf][3] + b1);
                if (sect == 1) {            // K: d-interleaved within 8-group
                    int db = dd & ~7;
                    dst[i0 + db + p0] = e00;  dst[i0 + db + p1] = e01;
                    dst[i1 + db + p0] = e10;  dst[i1 + db + p1] = e11;
                } else {                    // Q, V: plain
                    *(float2*)(dst + i0 + dd) = make_float2(e00, e01);
                    *(float2*)(dst + i1 + dd) = make_float2(e10, e11);
                }
            } else {         // final output: plain f32
                *(float2*)(out + (size_t)r0*C_ + col) =
                    make_float2(acc[mt][nf][0] + b0, acc[mt][nf][1] + b1);
                *(float2*)(out + (size_t)(r0+8)*C_ + col) =
                    make_float2(acc[mt][nf][2] + b0, acc[mt][nf][3] + b1);
            }
        }
    }
}

// ---------------------------------------------------------------------------
// Causal flash attention: 8 warps x 16 q-rows = 128-row block, 256 threads.
// g_k d-interleaved -> K fragments via LDS.64; P stored interleaved -> ap via
// LDS.64. 2-stage cp.async K/V ring; per-warp causal tile skip; exp2 softmax.
// ---------------------------------------------------------------------------
#define AK_LD 72
#define AV_LD 72
#define KS_SZ (64*AK_LD)
#define VS_SZ (64*AV_LD)
#define A_STAGE (KS_SZ + VS_SZ)
#define P_LD 72

__device__ __forceinline__ void attn_stage(float* sm, const float* Kg,
                                           const float* Vg, int kt, int tid)
{
    float* Ks = sm + (kt & 1) * A_STAGE;
    float* Vs = Ks + KS_SZ;
    const float* Kt = Kg + (size_t)(kt << 6) * D_;
    const float* Vt = Vg + (size_t)(kt << 6) * D_;
    const int r = tid >> 4, c = (tid & 15) << 2;
#pragma unroll
    for (int i = 0; i < 4; i++) {
        cp_async16(&Ks[(i*16 + r)*AK_LD + c], Kt + (i*16 + r)*D_ + c);
        cp_async16(&Vs[(i*16 + r)*AV_LD + c], Vt + (i*16 + r)*D_ + c);
    }
    CP_COMMIT();
}

__global__ __launch_bounds__(256, 2) void attn_mma()
{
    extern __shared__ float sm[];
    float* Ps = sm + 2*A_STAGE;          // per warp [16][P_LD]

    const int tid  = threadIdx.x;
    const int lane = tid & 31, w = tid >> 5;
    const int g = lane >> 2, ctg = lane & 3;
    const int qb = (gridDim.x - 1) - blockIdx.x;   // heavy blocks first
    const int bh = blockIdx.y;
    const int q0 = qb << 7;
    const int wq = q0 + (w << 4);                  // warp's 16 rows
    float* Pw = Ps + w * 16 * P_LD;

    const float* Qg = g_q + (size_t)bh * T_ * D_;
    const float* Kg = g_k + (size_t)bh * T_ * D_;
    const float* Vg = g_v + (size_t)bh * T_ * D_;

    // Q A-fragments; scale = 1/sqrt(64) * log2(e)  (exp2-domain softmax)
    const float qsc = 0.125f * 1.4426950408889634f;
    unsigned aq[8][4];
#pragma unroll
    for (int j = 0; j < 8; j++) {
        aq[j][0] = f2tf(Qg[(wq+g  )*D_ + (j<<3) + ctg    ] * qsc);
        aq[j][1] = f2tf(Qg[(wq+g+8)*D_ + (j<<3) + ctg    ] * qsc);
        aq[j][2] = f2tf(Qg[(wq+g  )*D_ + (j<<3) + ctg + 4] * qsc);
        aq[j][3] = f2tf(Qg[(wq+g+8)*D_ + (j<<3) + ctg + 4] * qsc);
    }

    float m_i[2] = {-1e30f, -1e30f};
    float l_i[2] = {0.f, 0.f};
    float o[8][4];
#pragma unroll
    for (int nf = 0; nf < 8; nf++)
#pragma unroll
        for (int r = 0; r < 4; r++) o[nf][r] = 0.f;

    const int p0 = ((ctg & 1) << 2) + (ctg >> 1), p1 = p0 + 2;

    const int nkt = (q0 >> 6) + 2;
    attn_stage(sm, Kg, Vg, 0, tid);

#pragma unroll 1
    for (int kt = 0; kt < nkt; kt++) {
        CP_WAIT(0);
        __syncthreads();
        if (kt + 1 < nkt) attn_stage(sm, Kg, Vg, kt + 1, tid);

        if ((kt << 6) <= wq + 15) {      // per-warp causal tile skip
            const float* Ksb = sm + (kt & 1) * A_STAGE;
            const float* Vsb = Ksb + KS_SZ;

            // S = Q K^T  (K interleaved -> LDS.64 fragment pairs)
            float s[8][4];
#pragma unroll
            for (int nf = 0; nf < 8; nf++)
#pragma unroll
                for (int r = 0; r < 4; r++) s[nf][r] = 0.f;
#pragma unroll
            for (int kk = 0; kk < 8; kk++) {
#pragma unroll
                for (int nf = 0; nf < 8; nf++) {
                    float2 bkv = *(const float2*)&Ksb[((nf<<3)+g)*AK_LD + (kk<<3) + (ctg<<1)];
                    unsigned bk[2] = { __float_as_uint(bkv.x), __float_as_uint(bkv.y) };
                    mma_tf32(s[nf], aq[kk], bk, s[nf]);
                }
            }

            // causal mask (diagonal-overlapping tiles only)
            if ((kt << 6) + 63 > wq) {
#pragma unroll
                for (int nf = 0; nf < 8; nf++) {
                    int col = (kt << 6) + (nf << 3) + (ctg << 1);
                    int r0 = wq + g, r1 = wq + g + 8;
                    if (col     > r0) s[nf][0] = -1e30f;
                    if (col + 1 > r0) s[nf][1] = -1e30f;
                    if (col     > r1) s[nf][2] = -1e30f;
                    if (col + 1 > r1) s[nf][3] = -1e30f;
                }
            }

            // online softmax (exp2 domain); a row lives on lanes 4g..4g+3
#pragma unroll
            for (int rr = 0; rr < 2; rr++) {
                float mx = -1e30f;
#pragma unroll
                for (int nf = 0; nf < 8; nf++)
                    mx = fmaxf(mx, fmaxf(s[nf][rr*2], s[nf][rr*2+1]));
                mx = fmaxf(mx, __shfl_xor_sync(0xffffffffu, mx, 1));
                mx = fmaxf(mx, __shfl_xor_sync(0xffffffffu, mx, 2));
                float mn = fmaxf(m_i[rr], mx);
                float alpha = exp2f(m_i[rr] - mn);
                m_i[rr] = mn;
                float rs = 0.f;
#pragma unroll
                for (int nf = 0; nf < 8; nf++) {
                    float pa = exp2f(s[nf][rr*2]   - mn);
                    float pb = exp2f(s[nf][rr*2+1] - mn);
                    s[nf][rr*2] = pa; s[nf][rr*2+1] = pb;
                    rs += pa + pb;
                }
                rs += __shfl_xor_sync(0xffffffffu, rs, 1);
                rs += __shfl_xor_sync(0xffffffffu, rs, 2);
                l_i[rr] = l_i[rr]*alpha + rs;
#pragma unroll
                for (int nf = 0; nf < 8; nf++) {
                    o[nf][rr*2]   *= alpha;
                    o[nf][rr*2+1] *= alpha;
                }
            }

            // P -> per-warp smem, interleaved within each 8-col group
#pragma unroll
            for (int nf = 0; nf < 8; nf++) {
                int cb = nf << 3;
                Pw[ g    *P_LD + cb + p0] = f2tf_f(s[nf][0]);
                Pw[ g    *P_LD + cb + p1] = f2tf_f(s[nf][1]);
                Pw[(g+8) *P_LD + cb + p0] = f2tf_f(s[nf][2]);
                Pw[(g+8) *P_LD + cb + p1] = f2tf_f(s[nf][3]);
            }
            __syncwarp();

            // O += P @ V  (P interleaved -> LDS.64 for ap)
#pragma unroll
            for (int kk = 0; kk < 8; kk++) {
                float2 a0 = *(const float2*)&Pw[ g    *P_LD + (kk<<3) + (ctg<<1)];
                float2 a1 = *(const float2*)&Pw[(g+8) *P_LD + (kk<<3) + (ctg<<1)];
                unsigned ap[4] = { __float_as_uint(a0.x), __float_as_uint(a1.x),
                                   __float_as_uint(a0.y), __float_as_uint(a1.y) };
#pragma unroll
                for (int nf = 0; nf < 8; nf++) {
                    unsigned bv[2];
                    bv[0] = __float_as_uint(Vsb[((kk<<3)+ctg  )*AV_LD + (nf<<3) + g]);
                    bv[1] = __float_as_uint(Vsb[((kk<<3)+ctg+4)*AV_LD + (nf<<3) + g]);
                    mma_tf32(o[nf], ap, bv, o[nf]);
                }
            }
        }
    }

    // epilogue: write [B*T, C] rounded + k-interleaved (packed proj input)
    const int b = bh >> 4, h = bh & 15;
    float inv0 = 1.0f / l_i[0], inv1 = 1.0f / l_i[1];
#pragma unroll
    for (int nf = 0; nf < 8; nf++) {
        size_t base0 = (size_t)(b*T_ + wq + g    )*C_ + (h << 6) + (nf << 3);
        size_t base1 = (size_t)(b*T_ + wq + g + 8)*C_ + (h << 6) + (nf << 3);
        g_ao[base0 + p0] = f2tf_f(o[nf][0]*inv0);
        g_ao[base0 + p1] = f2tf_f(o[nf][1]*inv0);
        g_ao[base1 + p0] = f2tf_f(o[nf][2]*inv1);
        g_ao[base1 + p1] = f2tf_f(o[nf][3]*inv1);
    }
}

// ---------------------------------------------------------------------------
extern "C" void kernel_launch(void* const* d_in, const int* in_sizes, int n_in,
                              void* d_out, int out_size)
{
    const float* x      = (const float*)d_in[0];
    const float* w_qkv  = (const float*)d_in[1];
    const float* b_qkv  = (const float*)d_in[2];
    const float* w_proj = (const float*)d_in[3];
    const float* b_proj = (const float*)d_in[4];
    float* out = (float*)d_out;

    float *x_p, *wq_p, *wp_p, *ao_p;
    cudaGetSymbolAddress((void**)&x_p,  g_x);
    cudaGetSymbolAddress((void**)&wq_p, g_wq);
    cudaGetSymbolAddress((void**)&wp_p, g_wp);
    cudaGetSymbolAddress((void**)&ao_p, g_ao);

    const int gemm_smem = 3 * G_STAGEW * (int)sizeof(float);              // 98304
    const int attn_smem = (2*A_STAGE + 8*16*P_LD) * (int)sizeof(float);   // 110592

    cudaFuncSetAttribute(mma_gemm<true>,
                         cudaFuncAttributeMaxDynamicSharedMemorySize, gemm_smem);
    cudaFuncSetAttribute(mma_gemm<false>,
                         cudaFuncAttributeMaxDynamicSharedMemorySize, gemm_smem);
    cudaFuncSetAttribute(attn_mma,
                         cudaFuncAttributeMaxDynamicSharedMemorySize, attn_smem);

    // prepack (one-time per call; memory-bound)
    pack_rows<<<M_*C_/8/256, 256>>>(x, x_p);
    pack_wt<<<dim3(3*C_/32, C_/32), dim3(32, 8)>>>(w_qkv, wq_p, 3*C_);
    pack_wt<<<dim3(C_/32, C_/32),   dim3(32, 8)>>>(w_proj, wp_p, C_);

    dim3 gq(24, 64);   // N=3072/128, M=8192/128
    mma_gemm<true><<<gq, 256, gemm_smem>>>(x_p, wq_p, b_qkv, nullptr);

    dim3 ga(16, 64);   // q-blocks (128 rows), B*H
    attn_mma<<<ga, 256, attn_smem>>>();

    dim3 gp(8, 64);    // N=1024/128, M=8192/128
    mma_gemm<false><<<gp, 256, gemm_smem>>>(ao_p, wp_p, b_proj, out);
}